// round 1
// baseline (speedup 1.0000x reference)
#include <cuda_runtime.h>
#include <math.h>

#define NGRID   64
#define NG3     (64*64*64)
#define ALPHA   0.34f
#define COULOMB 138.935456f
#define CUTOFF2 81.0f
#define PI_F    3.14159265358979323846f

// ---------------- device scratch (no allocations allowed) ----------------
__device__ float2 d_grid[NG3];      // complex FFT grid (2 MB)
__device__ float  g_ib[9];          // inv(box), row-major
__device__ float  g_bx[9];          // box copy
__device__ float  g_det;
__device__ float  g_bmod[NGRID];    // B-spline moduli (same for x,y,z; K=64)
__device__ double g_edir;           // direct + self + exclusion energy
__device__ double g_erec;           // raw reciprocal sum (pre-prefactor)

// ---------------- setup: zero grid, invert box, bmod table ----------------
__global__ void k_setup(const float* __restrict__ box) {
    int n = blockIdx.x * blockDim.x + threadIdx.x;
    if (n < NG3) d_grid[n] = make_float2(0.f, 0.f);
    if (blockIdx.x == 0) {
        if (threadIdx.x == 0) {
            float a = box[0], b = box[1], c = box[2];
            float d = box[3], e = box[4], f = box[5];
            float g = box[6], h = box[7], i = box[8];
            float det = a*(e*i - f*h) - b*(d*i - f*g) + c*(d*h - e*g);
            g_det = det;
            float inv = 1.f / det;
            g_ib[0] = (e*i - f*h) * inv; g_ib[1] = (c*h - b*i) * inv; g_ib[2] = (b*f - c*e) * inv;
            g_ib[3] = (f*g - d*i) * inv; g_ib[4] = (a*i - c*g) * inv; g_ib[5] = (c*d - a*f) * inv;
            g_ib[6] = (d*h - e*g) * inv; g_ib[7] = (b*g - a*h) * inv; g_ib[8] = (a*e - b*d) * inv;
            for (int k = 0; k < 9; k++) g_bx[k] = box[k];
            g_edir = 0.0;
            g_erec = 0.0;
        }
        if (threadIdx.x < NGRID) {
            // data = [M4(1), M4(2), M4(3)] = [1/6, 2/3, 1/6]; D(m)=|FFT|^2
            int m = threadIdx.x;
            float th = 2.f * PI_F * (float)m / (float)NGRID;
            float re = (1.f/6.f) + (2.f/3.f)*cosf(th) + (1.f/6.f)*cosf(2.f*th);
            float im = -((2.f/3.f)*sinf(th) + (1.f/6.f)*sinf(2.f*th));
            float d2 = re*re + im*im;
            g_bmod[m] = 1.f / fmaxf(d2, 1e-7f);
        }
    }
}

// ---------------- direct space + self + exclusion corrections ----------------
__global__ void k_direct(const float* __restrict__ pos, const float* __restrict__ q,
                         const int* __restrict__ excl, int N) {
    __shared__ float sx[256], sy[256], sz[256], sq[256];
    const int tx = threadIdx.x;
    const int i  = blockIdx.x * 256 + tx;
    const int jb = blockIdx.y * 256;

    float ib[9], bx[9];
#pragma unroll
    for (int k = 0; k < 9; k++) { ib[k] = g_ib[k]; bx[k] = g_bx[k]; }

    // load j tile
    int jl = jb + tx;
    sx[tx] = pos[3*jl + 0];
    sy[tx] = pos[3*jl + 1];
    sz[tx] = pos[3*jl + 2];
    sq[tx] = q[jl];
    __syncthreads();

    const float pxi = pos[3*i + 0], pyi = pos[3*i + 1], pzi = pos[3*i + 2];
    const float qi  = q[i];
    const int e0 = excl[2*i + 0];
    const int e1 = excl[2*i + 1];

    float pacc = 0.f;   // raw pair sum (double counted)
    float eacc = 0.f;   // self + exclusion (already scaled)

#pragma unroll 4
    for (int jj = 0; jj < 256; jj++) {
        int jg = jb + jj;
        float dx = pxi - sx[jj];
        float dy = pyi - sy[jj];
        float dz = pzi - sz[jj];
        // minimum image (general triclinic)
        float s0 = dx*ib[0] + dy*ib[3] + dz*ib[6];
        float s1 = dx*ib[1] + dy*ib[4] + dz*ib[7];
        float s2 = dx*ib[2] + dy*ib[5] + dz*ib[8];
        s0 -= rintf(s0); s1 -= rintf(s1); s2 -= rintf(s2);
        float ddx = s0*bx[0] + s1*bx[3] + s2*bx[6];
        float ddy = s0*bx[1] + s1*bx[4] + s2*bx[7];
        float ddz = s0*bx[2] + s1*bx[5] + s2*bx[8];
        float r2 = ddx*ddx + ddy*ddy + ddz*ddz;
        if (r2 < CUTOFF2 && jg != i && jg != e0 && jg != e1) {
            float r = sqrtf(r2);
            pacc += qi * sq[jj] * erfcf(ALPHA * r) / r;
        }
    }

    if (blockIdx.y == 0) {
        // self energy
        eacc += -COULOMB * ALPHA * 0.5641895835477563f * qi * qi; // 1/sqrt(pi)
        // exclusion correction
#pragma unroll
        for (int s = 0; s < 2; s++) {
            int e = (s == 0) ? e0 : e1;
            if (e >= 0) {
                float dx = pxi - pos[3*e + 0];
                float dy = pyi - pos[3*e + 1];
                float dz = pzi - pos[3*e + 2];
                float s0 = dx*ib[0] + dy*ib[3] + dz*ib[6];
                float s1 = dx*ib[1] + dy*ib[4] + dz*ib[7];
                float s2 = dx*ib[2] + dy*ib[5] + dz*ib[8];
                s0 -= rintf(s0); s1 -= rintf(s1); s2 -= rintf(s2);
                float ddx = s0*bx[0] + s1*bx[3] + s2*bx[6];
                float ddy = s0*bx[1] + s1*bx[4] + s2*bx[7];
                float ddz = s0*bx[2] + s1*bx[5] + s2*bx[8];
                float r2 = ddx*ddx + ddy*ddy + ddz*ddz;
                if (r2 > 0.f) {
                    float r = sqrtf(r2);
                    eacc += -0.5f * COULOMB * qi * q[e] * erff(ALPHA * r) / r;
                }
            }
        }
    }

    float tot = 0.5f * COULOMB * pacc + eacc;
    // warp reduce
#pragma unroll
    for (int off = 16; off > 0; off >>= 1)
        tot += __shfl_down_sync(0xffffffffu, tot, off);
    if ((tx & 31) == 0)
        atomicAdd(&g_edir, (double)tot);
}

// ---------------- B-spline charge spreading (order 4) ----------------
__global__ void k_spread(const float* __restrict__ pos, const float* __restrict__ q, int N) {
    int i = blockIdx.x * blockDim.x + threadIdx.x;
    if (i >= N) return;
    float ib[9];
#pragma unroll
    for (int k = 0; k < 9; k++) ib[k] = g_ib[k];

    float p0 = pos[3*i + 0], p1 = pos[3*i + 1], p2 = pos[3*i + 2];
    float f0 = p0*ib[0] + p1*ib[3] + p2*ib[6];
    float f1 = p0*ib[1] + p1*ib[4] + p2*ib[7];
    float f2 = p0*ib[2] + p1*ib[5] + p2*ib[8];
    f0 -= floorf(f0); f1 -= floorf(f1); f2 -= floorf(f2);

    float u[3] = { f0 * NGRID, f1 * NGRID, f2 * NGRID };
    int   base[3];
    float w[3][4];
#pragma unroll
    for (int d = 0; d < 3; d++) {
        float fu = floorf(u[d]);
        base[d] = (int)fu;
        float t = u[d] - fu;
        // order-2 -> order-3
        float w2_0 = 1.f - t, w2_1 = t;
        float n0 = 0.5f * (1.f - t) * w2_0;
        float n1 = 0.5f * ((t + 1.f) * w2_0 + (2.f - t) * w2_1);
        float n2 = 0.5f * t * w2_1;
        // order-3 -> order-4
        w[d][3] = (1.f/3.f) * t * n2;
        w[d][2] = (1.f/3.f) * ((t + 1.f) * n1 + (3.f - t) * n2);
        w[d][1] = (1.f/3.f) * ((t + 2.f) * n0 + (2.f - t) * n1);
        w[d][0] = (1.f/3.f) * (1.f - t) * n0;
    }
    float qi = q[i];
#pragma unroll
    for (int a = 0; a < 4; a++) {
        int ix = (base[0] + a + 61) & 63;
        float qa = qi * w[0][a];
#pragma unroll
        for (int b = 0; b < 4; b++) {
            int iy = (base[1] + b + 61) & 63;
            float qab = qa * w[1][b];
#pragma unroll
            for (int c = 0; c < 4; c++) {
                int iz = (base[2] + c + 61) & 63;
                int flat = ((ix << 6) | iy) << 6 | iz;
                atomicAdd(&d_grid[flat].x, qab * w[2][c]);
            }
        }
    }
}

// ---------------- 64-point DIF FFT along one axis (output bit-reversed) ----------------
__global__ void k_fft(int axis) {
    __shared__ float2 s[4][NGRID];
    const int line = blockIdx.x * 4 + threadIdx.y;
    const int t = threadIdx.x;
    const int a = line >> 6, b = line & 63;
    int base, stride;
    if (axis == 2)      { base = line << 6;        stride = 1;    }
    else if (axis == 1) { base = (a << 12) + b;    stride = 64;   }
    else                { base = (a << 6) + b;     stride = 4096; }

    float2* v = s[threadIdx.y];
    v[t] = d_grid[base + t * stride];
    __syncthreads();

#pragma unroll
    for (int len = 32; len >= 1; len >>= 1) {
        if (t < 32) {
            int j  = t & (len - 1);
            int i0 = ((t & ~(len - 1)) << 1) | j;
            int i1 = i0 + len;
            float2 u0 = v[i0], u1 = v[i1];
            float dr = u0.x - u1.x, di = u0.y - u1.y;
            float sn, cs;
            sincospif((float)j / (float)len, &sn, &cs);   // exp(-i*pi*j/len) = (cs, -sn)
            v[i0] = make_float2(u0.x + u1.x, u0.y + u1.y);
            v[i1] = make_float2(dr * cs + di * sn, di * cs - dr * sn);
        }
        __syncthreads();
    }
    d_grid[base + t * stride] = v[t];
}

// ---------------- reciprocal-space reduction (handles bit-reversed ordering) ----------------
__global__ void k_reduce() {
    int n = blockIdx.x * blockDim.x + threadIdx.x;  // 0 .. NG3-1
    int sxi = n >> 12, syi = (n >> 6) & 63, szi = n & 63;
    int mx = __brev((unsigned)sxi) >> 26;
    int my = __brev((unsigned)syi) >> 26;
    int mz = __brev((unsigned)szi) >> 26;
    float fx = (mx < 32) ? (float)mx : (float)(mx - 64);
    float fy = (my < 32) ? (float)my : (float)(my - 64);
    float fz = (mz < 32) ? (float)mz : (float)(mz - 64);

    float k0 = fx*g_ib[0] + fy*g_ib[1] + fz*g_ib[2];
    float k1 = fx*g_ib[3] + fy*g_ib[4] + fz*g_ib[5];
    float k2 = fx*g_ib[6] + fy*g_ib[7] + fz*g_ib[8];
    float msq = k0*k0 + k1*k1 + k2*k2;

    float2 F = d_grid[n];
    float sq = F.x*F.x + F.y*F.y;
    float val = 0.f;
    if (msq > 0.f) {
        float infl = expf(-(PI_F*PI_F) * msq / (ALPHA*ALPHA)) / msq;
        val = infl * g_bmod[mx] * g_bmod[my] * g_bmod[mz] * sq;
    }
#pragma unroll
    for (int off = 16; off > 0; off >>= 1)
        val += __shfl_down_sync(0xffffffffu, val, off);
    if ((threadIdx.x & 31) == 0)
        atomicAdd(&g_erec, (double)val);
}

// ---------------- finalize ----------------
__global__ void k_final(float* __restrict__ out) {
    double V = fabs((double)g_det);
    double erec = (double)COULOMB / (2.0 * 3.14159265358979323846 * V) * g_erec;
    out[0] = (float)(g_edir + erec);
}

// ---------------- launch ----------------
extern "C" void kernel_launch(void* const* d_in, const int* in_sizes, int n_in,
                              void* d_out, int out_size) {
    (void)n_in; (void)out_size;
    const float* pos  = (const float*)d_in[0];
    const float* q    = (const float*)d_in[1];
    const float* box  = (const float*)d_in[2];
    const int*   excl = (const int*)d_in[3];
    const int N = in_sizes[1];

    k_setup<<<NG3 / 256, 256>>>(box);
    dim3 dgrid(N / 256, N / 256);
    k_direct<<<dgrid, 256>>>(pos, q, excl, N);
    k_spread<<<(N + 255) / 256, 256>>>(pos, q, N);
    dim3 fblk(64, 4);
    k_fft<<<NG3 / 64 / 4, fblk>>>(2);
    k_fft<<<NG3 / 64 / 4, fblk>>>(1);
    k_fft<<<NG3 / 64 / 4, fblk>>>(0);
    k_reduce<<<NG3 / 256, 256>>>();
    k_final<<<1, 1>>>((float*)d_out);
}

// round 2
// speedup vs baseline: 1.4082x; 1.4082x over previous
#include <cuda_runtime.h>
#include <math.h>

#define NGRID   64
#define NG3     (64*64*64)
#define ALPHA   0.34f
#define COULOMB 138.935456f
#define CUTOFF2 81.0f
#define PI_F    3.14159265358979323846f

// ---------------- device scratch ----------------
__device__ float2 d_grid[NG3];      // complex FFT grid (2 MB)
__device__ float  g_ib[9];          // inv(box)
__device__ float  g_bx[9];          // box
__device__ float  g_det;
__device__ float  g_bmod[NGRID];    // B-spline moduli
__device__ double g_edir;
__device__ double g_erec;

// ---------------- setup ----------------
__global__ void k_setup(const float* __restrict__ box) {
    int n = blockIdx.x * blockDim.x + threadIdx.x;
    if (n < NG3) d_grid[n] = make_float2(0.f, 0.f);
    if (blockIdx.x == 0) {
        if (threadIdx.x == 0) {
            float a = box[0], b = box[1], c = box[2];
            float d = box[3], e = box[4], f = box[5];
            float g = box[6], h = box[7], i = box[8];
            float det = a*(e*i - f*h) - b*(d*i - f*g) + c*(d*h - e*g);
            g_det = det;
            float inv = 1.f / det;
            g_ib[0] = (e*i - f*h) * inv; g_ib[1] = (c*h - b*i) * inv; g_ib[2] = (b*f - c*e) * inv;
            g_ib[3] = (f*g - d*i) * inv; g_ib[4] = (a*i - c*g) * inv; g_ib[5] = (c*d - a*f) * inv;
            g_ib[6] = (d*h - e*g) * inv; g_ib[7] = (b*g - a*h) * inv; g_ib[8] = (a*e - b*d) * inv;
            for (int k = 0; k < 9; k++) g_bx[k] = box[k];
            g_edir = 0.0;
            g_erec = 0.0;
        }
        if (threadIdx.x < NGRID) {
            int m = threadIdx.x;
            float th = 2.f * PI_F * (float)m / (float)NGRID;
            float re = (1.f/6.f) + (2.f/3.f)*cosf(th) + (1.f/6.f)*cosf(2.f*th);
            float im = -((2.f/3.f)*sinf(th) + (1.f/6.f)*sinf(2.f*th));
            g_bmod[m] = 1.f / fmaxf(re*re + im*im, 1e-7f);
        }
    }
}

// ---------------- direct space (triangular tiles, orthorhombic min-image) ----------------
__global__ void __launch_bounds__(256) k_direct(const float* __restrict__ pos,
                                                const float* __restrict__ q,
                                                const int* __restrict__ excl, int N) {
    const int bi = blockIdx.x, bj = blockIdx.y;
    if (bj < bi) return;
    __shared__ float4 sp[256];
    const int tx = threadIdx.x;
    const int i  = bi * 256 + tx;
    const int jb = bj * 256;

    int jl = jb + tx;
    sp[tx] = make_float4(pos[3*jl + 0], pos[3*jl + 1], pos[3*jl + 2], q[jl]);
    __syncthreads();

    // orthorhombic box (input box is diagonal)
    const float Lx = g_bx[0], Ly = g_bx[4], Lz = g_bx[8];
    const float iLx = g_ib[0], iLy = g_ib[4], iLz = g_ib[8];

    const float pxi = pos[3*i + 0], pyi = pos[3*i + 1], pzi = pos[3*i + 2];
    const float qi  = q[i];
    const int e0 = excl[2*i + 0];
    const int e1 = excl[2*i + 1];

    float pacc = 0.f;
#pragma unroll 8
    for (int jj = 0; jj < 256; jj++) {
        float4 pj = sp[jj];
        float dx = pxi - pj.x;
        float dy = pyi - pj.y;
        float dz = pzi - pj.z;
        dx -= Lx * rintf(dx * iLx);
        dy -= Ly * rintf(dy * iLy);
        dz -= Lz * rintf(dz * iLz);
        float r2 = dx*dx + dy*dy + dz*dz;
        int jg = jb + jj;
        if (r2 < CUTOFF2 && jg != i && jg != e0 && jg != e1) {
            float rinv = rsqrtf(r2);
            float r = r2 * rinv;
            pacc += pj.w * erfcf(ALPHA * r) * rinv;
        }
    }
    pacc *= qi;

    float eacc = 0.f;
    if (bi == bj) {
        eacc += -COULOMB * ALPHA * 0.5641895835477563f * qi * qi;  // self, 1/sqrt(pi)
#pragma unroll
        for (int s = 0; s < 2; s++) {
            int e = (s == 0) ? e0 : e1;
            if (e >= 0) {
                float dx = pxi - pos[3*e + 0];
                float dy = pyi - pos[3*e + 1];
                float dz = pzi - pos[3*e + 2];
                dx -= Lx * rintf(dx * iLx);
                dy -= Ly * rintf(dy * iLy);
                dz -= Lz * rintf(dz * iLz);
                float r2 = dx*dx + dy*dy + dz*dz;
                if (r2 > 0.f) {
                    float rinv = rsqrtf(r2);
                    float r = r2 * rinv;
                    eacc += -0.5f * COULOMB * qi * q[e] * erff(ALPHA * r) * rinv;
                }
            }
        }
    }

    float wt = (bi == bj) ? 0.5f : 1.0f;
    float tot = COULOMB * wt * pacc + eacc;
#pragma unroll
    for (int off = 16; off > 0; off >>= 1)
        tot += __shfl_down_sync(0xffffffffu, tot, off);
    if ((tx & 31) == 0)
        atomicAdd(&g_edir, (double)tot);
}

// ---------------- B-spline spread (order 4) ----------------
__global__ void k_spread(const float* __restrict__ pos, const float* __restrict__ q, int N) {
    int i = blockIdx.x * blockDim.x + threadIdx.x;
    if (i >= N) return;
    float ib[9];
#pragma unroll
    for (int k = 0; k < 9; k++) ib[k] = g_ib[k];

    float p0 = pos[3*i + 0], p1 = pos[3*i + 1], p2 = pos[3*i + 2];
    float f0 = p0*ib[0] + p1*ib[3] + p2*ib[6];
    float f1 = p0*ib[1] + p1*ib[4] + p2*ib[7];
    float f2 = p0*ib[2] + p1*ib[5] + p2*ib[8];
    f0 -= floorf(f0); f1 -= floorf(f1); f2 -= floorf(f2);

    float u[3] = { f0 * NGRID, f1 * NGRID, f2 * NGRID };
    int   base[3];
    float w[3][4];
#pragma unroll
    for (int d = 0; d < 3; d++) {
        float fu = floorf(u[d]);
        base[d] = (int)fu;
        float t = u[d] - fu;
        float w2_0 = 1.f - t, w2_1 = t;
        float n0 = 0.5f * (1.f - t) * w2_0;
        float n1 = 0.5f * ((t + 1.f) * w2_0 + (2.f - t) * w2_1);
        float n2 = 0.5f * t * w2_1;
        w[d][3] = (1.f/3.f) * t * n2;
        w[d][2] = (1.f/3.f) * ((t + 1.f) * n1 + (3.f - t) * n2);
        w[d][1] = (1.f/3.f) * ((t + 2.f) * n0 + (2.f - t) * n1);
        w[d][0] = (1.f/3.f) * (1.f - t) * n0;
    }
    float qi = q[i];
#pragma unroll
    for (int a = 0; a < 4; a++) {
        int ix = (base[0] + a + 61) & 63;
        float qa = qi * w[0][a];
#pragma unroll
        for (int b = 0; b < 4; b++) {
            int iy = (base[1] + b + 61) & 63;
            float qab = qa * w[1][b];
#pragma unroll
            for (int c = 0; c < 4; c++) {
                int iz = (base[2] + c + 61) & 63;
                int flat = ((ix << 6) | iy) << 6 | iz;
                atomicAdd(&d_grid[flat].x, qab * w[2][c]);
            }
        }
    }
}

// ---------------- 64-pt DIF FFT over a warp (output bit-reversed) ----------------
__device__ __forceinline__ void fft64(float2* p, int stride, int t, const float2* __restrict__ tw) {
#pragma unroll
    for (int len = 32; len >= 1; len >>= 1) {
        int j  = t & (len - 1);
        int i0 = ((t & ~(len - 1)) << 1) | j;
        int i1 = i0 + len;
        float2 u0 = p[i0 * stride], u1 = p[i1 * stride];
        float2 w  = tw[j * (32 / len)];       // exp(-i*pi*j/len)
        float dr = u0.x - u1.x, di = u0.y - u1.y;
        p[i0 * stride] = make_float2(u0.x + u1.x, u0.y + u1.y);
        p[i1 * stride] = make_float2(dr * w.x - di * w.y, dr * w.y + di * w.x);
        __syncwarp();
    }
}

// ---------------- fused z + y FFT passes: one CTA per x-plane ----------------
__global__ void __launch_bounds__(512) k_fft_zy() {
    __shared__ float2 v[64 * 65];   // padded rows: [y][z] at y*65+z
    __shared__ float2 tw[32];
    const int tid  = threadIdx.x;
    const int lane = tid & 31, w = tid >> 5;       // 16 warps
    if (tid < 32) {
        float s, c; sincospif((float)tid / 32.f, &s, &c);
        tw[tid] = make_float2(c, -s);
    }
    float2* gp = d_grid + (blockIdx.x << 12);
    for (int k = tid; k < 4096; k += 512) {
        int y = k >> 6, z = k & 63;
        v[y * 65 + z] = gp[k];
    }
    __syncthreads();
    // z-FFTs (stride 1), 4 lines per warp
#pragma unroll
    for (int l = 0; l < 4; l++)
        fft64(v + (w + 16 * l) * 65, 1, lane, tw);
    __syncthreads();
    // y-FFTs (stride 65), fixed z
#pragma unroll
    for (int l = 0; l < 4; l++)
        fft64(v + (w + 16 * l), 65, lane, tw);
    __syncthreads();
    for (int k = tid; k < 4096; k += 512) {
        int y = k >> 6, z = k & 63;
        gp[k] = v[y * 65 + z];
    }
}

__device__ __forceinline__ int brev6(int x) { return (int)(__brev((unsigned)x) >> 26); }

__device__ __forceinline__ float recip_contrib(float2 F, int mx, int my, int mz,
                                               const float* bm, const float* ib) {
    float fx = (mx < 32) ? (float)mx : (float)(mx - 64);
    float fy = (my < 32) ? (float)my : (float)(my - 64);
    float fz = (mz < 32) ? (float)mz : (float)(mz - 64);
    float k0 = fx*ib[0] + fy*ib[1] + fz*ib[2];
    float k1 = fx*ib[3] + fy*ib[4] + fz*ib[5];
    float k2 = fx*ib[6] + fy*ib[7] + fz*ib[8];
    float msq = k0*k0 + k1*k1 + k2*k2;
    if (msq <= 0.f) return 0.f;
    float infl = __expf(-(PI_F*PI_F) * msq / (ALPHA*ALPHA)) / msq;
    return infl * bm[mx] * bm[my] * bm[mz] * (F.x*F.x + F.y*F.y);
}

// ---------------- fused x FFT pass + reciprocal reduction ----------------
__global__ void __launch_bounds__(512) k_fft_x_red() {
    __shared__ float2 s[16][64];
    __shared__ float2 tw[32];
    __shared__ float  bm[64];
    __shared__ float  ib[9];
    __shared__ float  partial[16];
    const int lane = threadIdx.x;          // 0..31
    const int w    = threadIdx.y;          // 0..15
    const int tid  = w * 32 + lane;
    if (tid < 32) {
        float sn, cs; sincospif((float)tid / 32.f, &sn, &cs);
        tw[tid] = make_float2(cs, -sn);
    }
    if (tid < 64) bm[tid] = g_bmod[tid];
    if (tid < 9)  ib[tid] = g_ib[tid];
    __syncthreads();

    const int line = blockIdx.x * 16 + w;      // = y_storage*64 + z_storage
    float2* p = s[w];
    p[lane]      = d_grid[lane * 4096 + line];
    p[lane + 32] = d_grid[(lane + 32) * 4096 + line];
    __syncwarp();
    fft64(p, 1, lane, tw);

    const int my = brev6(line >> 6);
    const int mz = brev6(line & 63);
    float val = recip_contrib(p[lane],      brev6(lane),      my, mz, bm, ib)
              + recip_contrib(p[lane + 32], brev6(lane + 32), my, mz, bm, ib);
#pragma unroll
    for (int off = 16; off > 0; off >>= 1)
        val += __shfl_down_sync(0xffffffffu, val, off);
    if (lane == 0) partial[w] = val;
    __syncthreads();
    if (tid < 16) {
        float v = partial[tid];
#pragma unroll
        for (int off = 8; off > 0; off >>= 1)
            v += __shfl_down_sync(0xffffu, v, off);
        if (tid == 0) atomicAdd(&g_erec, (double)v);
    }
}

// ---------------- finalize ----------------
__global__ void k_final(float* __restrict__ out) {
    double V = fabs((double)g_det);
    double erec = (double)COULOMB / (2.0 * 3.14159265358979323846 * V) * g_erec;
    out[0] = (float)(g_edir + erec);
}

// ---------------- launch ----------------
extern "C" void kernel_launch(void* const* d_in, const int* in_sizes, int n_in,
                              void* d_out, int out_size) {
    (void)n_in; (void)out_size;
    const float* pos  = (const float*)d_in[0];
    const float* q    = (const float*)d_in[1];
    const float* box  = (const float*)d_in[2];
    const int*   excl = (const int*)d_in[3];
    const int N = in_sizes[1];

    k_setup<<<NG3 / 256, 256>>>(box);
    dim3 dgrid(N / 256, N / 256);
    k_direct<<<dgrid, 256>>>(pos, q, excl, N);
    k_spread<<<(N + 255) / 256, 256>>>(pos, q, N);
    k_fft_zy<<<64, 512>>>();
    dim3 xblk(32, 16);
    k_fft_x_red<<<4096 / 16, xblk>>>();
    k_final<<<1, 1>>>((float*)d_out);
}

// round 3
// speedup vs baseline: 2.0981x; 1.4899x over previous
#include <cuda_runtime.h>
#include <math.h>

#define NGRID   64
#define NG3     (64*64*64)
#define ALPHA   0.34f
#define COULOMB 138.935456f
#define CUTOFF2 81.0f
#define PI_F    3.14159265358979323846f

// ---------------- device scratch ----------------
__device__ float2 d_grid[NG3];      // complex FFT grid (2 MB)
__device__ float  g_ib[9];          // inv(box)
__device__ float  g_bx[9];          // box
__device__ float  g_det;
__device__ float  g_bmod[NGRID];    // B-spline moduli
__device__ double g_edir;
__device__ double g_erec;

// ---------------- setup ----------------
__global__ void k_setup(const float* __restrict__ box) {
    int n = blockIdx.x * blockDim.x + threadIdx.x;
    if (n < NG3) d_grid[n] = make_float2(0.f, 0.f);
    if (blockIdx.x == 0) {
        if (threadIdx.x == 0) {
            float a = box[0], b = box[1], c = box[2];
            float d = box[3], e = box[4], f = box[5];
            float g = box[6], h = box[7], i = box[8];
            float det = a*(e*i - f*h) - b*(d*i - f*g) + c*(d*h - e*g);
            g_det = det;
            float inv = 1.f / det;
            g_ib[0] = (e*i - f*h) * inv; g_ib[1] = (c*h - b*i) * inv; g_ib[2] = (b*f - c*e) * inv;
            g_ib[3] = (f*g - d*i) * inv; g_ib[4] = (a*i - c*g) * inv; g_ib[5] = (c*d - a*f) * inv;
            g_ib[6] = (d*h - e*g) * inv; g_ib[7] = (b*g - a*h) * inv; g_ib[8] = (a*e - b*d) * inv;
            for (int k = 0; k < 9; k++) g_bx[k] = box[k];
            g_edir = 0.0;
            g_erec = 0.0;
        }
        if (threadIdx.x < NGRID) {
            int m = threadIdx.x;
            float th = 2.f * PI_F * (float)m / (float)NGRID;
            float re = (1.f/6.f) + (2.f/3.f)*cosf(th) + (1.f/6.f)*cosf(2.f*th);
            float im = -((2.f/3.f)*sinf(th) + (1.f/6.f)*sinf(2.f*th));
            g_bmod[m] = 1.f / fmaxf(re*re + im*im, 1e-7f);
        }
    }
}

// ---------------- direct space (triangular tiles, orthorhombic min-image) ----------------
__global__ void __launch_bounds__(256) k_direct(const float* __restrict__ pos,
                                                const float* __restrict__ q,
                                                const int* __restrict__ excl, int N) {
    const int bi = blockIdx.x, bj = blockIdx.y;
    if (bj < bi) return;
    __shared__ float4 sp[256];
    const int tx = threadIdx.x;
    const int i  = bi * 256 + tx;
    const int jb = bj * 256;

    int jl = jb + tx;
    sp[tx] = make_float4(pos[3*jl + 0], pos[3*jl + 1], pos[3*jl + 2], q[jl]);
    __syncthreads();

    const float Lx = g_bx[0], Ly = g_bx[4], Lz = g_bx[8];
    const float iLx = g_ib[0], iLy = g_ib[4], iLz = g_ib[8];

    const float pxi = pos[3*i + 0], pyi = pos[3*i + 1], pzi = pos[3*i + 2];
    const float qi  = q[i];
    const int e0 = excl[2*i + 0];
    const int e1 = excl[2*i + 1];

    float pacc = 0.f;
#pragma unroll 8
    for (int jj = 0; jj < 256; jj++) {
        float4 pj = sp[jj];
        float dx = pxi - pj.x;
        float dy = pyi - pj.y;
        float dz = pzi - pj.z;
        dx -= Lx * rintf(dx * iLx);
        dy -= Ly * rintf(dy * iLy);
        dz -= Lz * rintf(dz * iLz);
        float r2 = dx*dx + dy*dy + dz*dz;
        int jg = jb + jj;
        if (r2 < CUTOFF2 && jg != i && jg != e0 && jg != e1) {
            float rinv = rsqrtf(r2);
            float r = r2 * rinv;
            pacc += pj.w * erfcf(ALPHA * r) * rinv;
        }
    }
    pacc *= qi;

    float eacc = 0.f;
    if (bi == bj) {
        eacc += -COULOMB * ALPHA * 0.5641895835477563f * qi * qi;  // self
#pragma unroll
        for (int s = 0; s < 2; s++) {
            int e = (s == 0) ? e0 : e1;
            if (e >= 0) {
                float dx = pxi - pos[3*e + 0];
                float dy = pyi - pos[3*e + 1];
                float dz = pzi - pos[3*e + 2];
                dx -= Lx * rintf(dx * iLx);
                dy -= Ly * rintf(dy * iLy);
                dz -= Lz * rintf(dz * iLz);
                float r2 = dx*dx + dy*dy + dz*dz;
                if (r2 > 0.f) {
                    float rinv = rsqrtf(r2);
                    float r = r2 * rinv;
                    eacc += -0.5f * COULOMB * qi * q[e] * erff(ALPHA * r) * rinv;
                }
            }
        }
    }

    float wt = (bi == bj) ? 0.5f : 1.0f;
    float tot = COULOMB * wt * pacc + eacc;
#pragma unroll
    for (int off = 16; off > 0; off >>= 1)
        tot += __shfl_down_sync(0xffffffffu, tot, off);
    if ((tx & 31) == 0)
        atomicAdd(&g_edir, (double)tot);
}

// ---------------- B-spline spread (order 4) ----------------
__global__ void k_spread(const float* __restrict__ pos, const float* __restrict__ q, int N) {
    int i = blockIdx.x * blockDim.x + threadIdx.x;
    if (i >= N) return;
    float ib[9];
#pragma unroll
    for (int k = 0; k < 9; k++) ib[k] = g_ib[k];

    float p0 = pos[3*i + 0], p1 = pos[3*i + 1], p2 = pos[3*i + 2];
    float f0 = p0*ib[0] + p1*ib[3] + p2*ib[6];
    float f1 = p0*ib[1] + p1*ib[4] + p2*ib[7];
    float f2 = p0*ib[2] + p1*ib[5] + p2*ib[8];
    f0 -= floorf(f0); f1 -= floorf(f1); f2 -= floorf(f2);

    float u[3] = { f0 * NGRID, f1 * NGRID, f2 * NGRID };
    int   base[3];
    float w[3][4];
#pragma unroll
    for (int d = 0; d < 3; d++) {
        float fu = floorf(u[d]);
        base[d] = (int)fu;
        float t = u[d] - fu;
        float w2_0 = 1.f - t, w2_1 = t;
        float n0 = 0.5f * (1.f - t) * w2_0;
        float n1 = 0.5f * ((t + 1.f) * w2_0 + (2.f - t) * w2_1);
        float n2 = 0.5f * t * w2_1;
        w[d][3] = (1.f/3.f) * t * n2;
        w[d][2] = (1.f/3.f) * ((t + 1.f) * n1 + (3.f - t) * n2);
        w[d][1] = (1.f/3.f) * ((t + 2.f) * n0 + (2.f - t) * n1);
        w[d][0] = (1.f/3.f) * (1.f - t) * n0;
    }
    float qi = q[i];
#pragma unroll
    for (int a = 0; a < 4; a++) {
        int ix = (base[0] + a + 61) & 63;
        float qa = qi * w[0][a];
#pragma unroll
        for (int b = 0; b < 4; b++) {
            int iy = (base[1] + b + 61) & 63;
            float qab = qa * w[1][b];
#pragma unroll
            for (int c = 0; c < 4; c++) {
                int iz = (base[2] + c + 61) & 63;
                int flat = ((ix << 6) | iy) << 6 | iz;
                atomicAdd(&d_grid[flat].x, qab * w[2][c]);
            }
        }
    }
}

// ---------------- register-resident 64-pt DIF FFT (warp collective, out bit-reversed) ----
__device__ __forceinline__ void bfly_local(float2& a, float2& b, float2 w) {
    float dr = a.x - b.x, di = a.y - b.y;
    a.x += b.x; a.y += b.y;
    b.x = dr * w.x - di * w.y;
    b.y = dr * w.y + di * w.x;
}
__device__ __forceinline__ float2 bfly_shfl(float2 v, int len, int lane, float2 w) {
    float ox = __shfl_xor_sync(0xffffffffu, v.x, len);
    float oy = __shfl_xor_sync(0xffffffffu, v.y, len);
    if ((lane & len) == 0) {
        return make_float2(v.x + ox, v.y + oy);
    } else {
        float dr = ox - v.x, di = oy - v.y;
        return make_float2(dr * w.x - di * w.y, dr * w.y + di * w.x);
    }
}
// tw[k] = exp(-i*pi*k/32)
__device__ __forceinline__ void fft64_reg(float2& a, float2& b, int lane,
                                          const float2* __restrict__ tw) {
    bfly_local(a, b, tw[lane]);                 // stage len=32 (both elems in-lane)
#pragma unroll
    for (int len = 16; len >= 1; len >>= 1) {   // stages via shuffle
        float2 w = tw[(lane & (len - 1)) * (32 / len)];
        a = bfly_shfl(a, len, lane, w);
        b = bfly_shfl(b, len, lane, w);
    }
}

// ---------------- fused z + y FFT passes: one CTA per x-plane, 32 warps ----------------
__global__ void __launch_bounds__(1024) k_fft_zy() {
    __shared__ float2 v[64 * 65];   // [y][z] at y*65+z (pad avoids column conflicts)
    __shared__ float2 tw[32];
    const int tid  = threadIdx.x;
    const int lane = tid & 31, w = tid >> 5;   // 32 warps
    if (tid < 32) {
        float s, c; sincospif((float)tid / 32.f, &s, &c);
        tw[tid] = make_float2(c, -s);
    }
    float2* gp = d_grid + (blockIdx.x << 12);
    for (int k = tid; k < 4096; k += 1024) {
        int y = k >> 6, z = k & 63;
        v[y * 65 + z] = gp[k];
    }
    __syncthreads();
    // z-FFTs: rows y = w, w+32
#pragma unroll
    for (int l = 0; l < 2; l++) {
        float2* p = v + (w + 32 * l) * 65;
        float2 a = p[lane], b = p[lane + 32];
        fft64_reg(a, b, lane, tw);
        p[lane] = a; p[lane + 32] = b;
    }
    __syncthreads();
    // y-FFTs: columns z = w, w+32
#pragma unroll
    for (int l = 0; l < 2; l++) {
        float2* p = v + (w + 32 * l);
        float2 a = p[lane * 65], b = p[(lane + 32) * 65];
        fft64_reg(a, b, lane, tw);
        p[lane * 65] = a; p[(lane + 32) * 65] = b;
    }
    __syncthreads();
    for (int k = tid; k < 4096; k += 1024) {
        int y = k >> 6, z = k & 63;
        gp[k] = v[y * 65 + z];
    }
}

__device__ __forceinline__ int brev6(int x) { return (int)(__brev((unsigned)x) >> 26); }

__device__ __forceinline__ float recip_contrib(float2 F, int mx, int my, int mz,
                                               const float* bm, const float* ib) {
    float fx = (mx < 32) ? (float)mx : (float)(mx - 64);
    float fy = (my < 32) ? (float)my : (float)(my - 64);
    float fz = (mz < 32) ? (float)mz : (float)(mz - 64);
    float k0 = fx*ib[0] + fy*ib[1] + fz*ib[2];
    float k1 = fx*ib[3] + fy*ib[4] + fz*ib[5];
    float k2 = fx*ib[6] + fy*ib[7] + fz*ib[8];
    float msq = k0*k0 + k1*k1 + k2*k2;
    if (msq <= 0.f) return 0.f;
    float infl = __expf(-(PI_F*PI_F) * msq / (ALPHA*ALPHA)) / msq;
    return infl * bm[mx] * bm[my] * bm[mz] * (F.x*F.x + F.y*F.y);
}

// ---------------- x FFT pass fused with reciprocal reduction ----------------
__global__ void __launch_bounds__(256) k_fft_x_red() {
    __shared__ float2 tw[32];
    __shared__ float  bm[64];
    __shared__ float  ib[9];
    __shared__ float  partial[8];
    const int tid  = threadIdx.x;
    const int lane = tid & 31, w = tid >> 5;   // 8 warps
    if (tid < 32) {
        float sn, cs; sincospif((float)tid / 32.f, &sn, &cs);
        tw[tid] = make_float2(cs, -sn);
    }
    if (tid < 64) bm[tid] = g_bmod[tid];
    if (tid < 9)  ib[tid] = g_ib[tid];
    __syncthreads();

    const int line = blockIdx.x * 8 + w;       // = y_storage*64 + z_storage
    float2 a = d_grid[lane * 4096 + line];
    float2 b = d_grid[(lane + 32) * 4096 + line];
    fft64_reg(a, b, lane, tw);

    const int my = brev6(line >> 6);
    const int mz = brev6(line & 63);
    float val = recip_contrib(a, brev6(lane),      my, mz, bm, ib)
              + recip_contrib(b, brev6(lane + 32), my, mz, bm, ib);
#pragma unroll
    for (int off = 16; off > 0; off >>= 1)
        val += __shfl_down_sync(0xffffffffu, val, off);
    if (lane == 0) partial[w] = val;
    __syncthreads();
    if (tid < 8) {
        float x = partial[tid];
#pragma unroll
        for (int off = 4; off > 0; off >>= 1)
            x += __shfl_down_sync(0xffu, x, off);
        if (tid == 0) atomicAdd(&g_erec, (double)x);
    }
}

// ---------------- finalize ----------------
__global__ void k_final(float* __restrict__ out) {
    double V = fabs((double)g_det);
    double erec = (double)COULOMB / (2.0 * 3.14159265358979323846 * V) * g_erec;
    out[0] = (float)(g_edir + erec);
}

// ---------------- launch (fork direct onto side stream, join before final) -------------
extern "C" void kernel_launch(void* const* d_in, const int* in_sizes, int n_in,
                              void* d_out, int out_size) {
    (void)n_in; (void)out_size;
    const float* pos  = (const float*)d_in[0];
    const float* q    = (const float*)d_in[1];
    const float* box  = (const float*)d_in[2];
    const int*   excl = (const int*)d_in[3];
    const int N = in_sizes[1];

    static cudaStream_t s_side = nullptr;
    static cudaEvent_t  ev_fork = nullptr, ev_join = nullptr;
    if (!s_side) {
        cudaStreamCreateWithFlags(&s_side, cudaStreamNonBlocking);
        cudaEventCreateWithFlags(&ev_fork, cudaEventDisableTiming);
        cudaEventCreateWithFlags(&ev_join, cudaEventDisableTiming);
    }

    k_setup<<<NG3 / 256, 256>>>(box);

    // fork: direct-space on side stream, reciprocal chain on main stream
    cudaEventRecord(ev_fork, 0);
    cudaStreamWaitEvent(s_side, ev_fork, 0);
    dim3 dgrid(N / 256, N / 256);
    k_direct<<<dgrid, 256, 0, s_side>>>(pos, q, excl, N);
    cudaEventRecord(ev_join, s_side);

    k_spread<<<(N + 255) / 256, 256>>>(pos, q, N);
    k_fft_zy<<<64, 1024>>>();
    k_fft_x_red<<<4096 / 8, 256>>>();

    cudaStreamWaitEvent(0, ev_join, 0);
    k_final<<<1, 1>>>((float*)d_out);
}

// round 4
// speedup vs baseline: 3.1695x; 1.5107x over previous
#include <cuda_runtime.h>
#include <math.h>

#define NGRID   64
#define NG3     (64*64*64)
#define ALPHA   0.34f
#define COULOMB 138.935456f
#define CUTOFF2 81.0f
#define PI_F    3.14159265358979323846f
#define DTILE   128

// ---------------- device scratch ----------------
__device__ float2 d_grid[NG3];      // complex FFT grid (2 MB)
__device__ float  g_ib[9];          // inv(box)
__device__ float  g_bx[9];          // box
__device__ float  g_det;
__device__ float  g_bmod[NGRID];    // B-spline moduli
__device__ double g_edir;
__device__ double g_erec;

// ---------------- setup ----------------
__global__ void k_setup(const float* __restrict__ box) {
    int n = blockIdx.x * blockDim.x + threadIdx.x;
    if (n < NG3) d_grid[n] = make_float2(0.f, 0.f);
    if (blockIdx.x == 0) {
        if (threadIdx.x == 0) {
            float a = box[0], b = box[1], c = box[2];
            float d = box[3], e = box[4], f = box[5];
            float g = box[6], h = box[7], i = box[8];
            float det = a*(e*i - f*h) - b*(d*i - f*g) + c*(d*h - e*g);
            g_det = det;
            float inv = 1.f / det;
            g_ib[0] = (e*i - f*h) * inv; g_ib[1] = (c*h - b*i) * inv; g_ib[2] = (b*f - c*e) * inv;
            g_ib[3] = (f*g - d*i) * inv; g_ib[4] = (a*i - c*g) * inv; g_ib[5] = (c*d - a*f) * inv;
            g_ib[6] = (d*h - e*g) * inv; g_ib[7] = (b*g - a*h) * inv; g_ib[8] = (a*e - b*d) * inv;
            for (int k = 0; k < 9; k++) g_bx[k] = box[k];
            g_edir = 0.0;
            g_erec = 0.0;
        }
        if (threadIdx.x < NGRID) {
            int m = threadIdx.x;
            float th = 2.f * PI_F * (float)m / (float)NGRID;
            float re = (1.f/6.f) + (2.f/3.f)*cosf(th) + (1.f/6.f)*cosf(2.f*th);
            float im = -((2.f/3.f)*sinf(th) + (1.f/6.f)*sinf(2.f*th));
            g_bmod[m] = 1.f / fmaxf(re*re + im*im, 1e-7f);
        }
    }
}

// Abramowitz-Stegun 7.1.26: |err| <= 1.5e-7 absolute, x >= 0
__device__ __forceinline__ float fast_erfc(float x) {
    float t = __fdividef(1.0f, fmaf(0.3275911f, x, 1.0f));
    float p = fmaf(1.061405429f, t, -1.453152027f);
    p = fmaf(p, t, 1.421413741f);
    p = fmaf(p, t, -0.284496736f);
    p = fmaf(p, t, 0.254829592f);
    return p * t * __expf(-x * x);
}

// ---------------- direct space (triangular 128x128 tiles, orthorhombic) ----------------
__global__ void __launch_bounds__(DTILE) k_direct(const float* __restrict__ pos,
                                                  const float* __restrict__ q,
                                                  const int* __restrict__ excl, int N) {
    const int bi = blockIdx.x, bj = blockIdx.y;
    if (bj < bi) return;
    __shared__ float4 sp[DTILE];
    const int tx = threadIdx.x;
    const int i  = bi * DTILE + tx;
    const int jb = bj * DTILE;

    int jl = jb + tx;
    sp[tx] = make_float4(pos[3*jl + 0], pos[3*jl + 1], pos[3*jl + 2], q[jl]);
    __syncthreads();

    const float Lx = g_bx[0], Ly = g_bx[4], Lz = g_bx[8];
    const float iLx = g_ib[0], iLy = g_ib[4], iLz = g_ib[8];

    const float pxi = pos[3*i + 0], pyi = pos[3*i + 1], pzi = pos[3*i + 2];
    const float qi  = q[i];
    const int e0 = excl[2*i + 0];
    const int e1 = excl[2*i + 1];

    float pacc = 0.f;
#pragma unroll 4
    for (int jj = 0; jj < DTILE; jj++) {
        float4 pj = sp[jj];
        float dx = pxi - pj.x;
        float dy = pyi - pj.y;
        float dz = pzi - pj.z;
        dx -= Lx * rintf(dx * iLx);
        dy -= Ly * rintf(dy * iLy);
        dz -= Lz * rintf(dz * iLz);
        float r2 = dx*dx + dy*dy + dz*dz;
        int jg = jb + jj;
        if (r2 < CUTOFF2 && jg != i && jg != e0 && jg != e1) {
            float rinv = rsqrtf(r2);
            pacc += pj.w * fast_erfc(ALPHA * r2 * rinv) * rinv;
        }
    }
    pacc *= qi;

    float eacc = 0.f;
    if (bi == bj) {
        eacc += -COULOMB * ALPHA * 0.5641895835477563f * qi * qi;  // self
#pragma unroll
        for (int s = 0; s < 2; s++) {
            int e = (s == 0) ? e0 : e1;
            if (e >= 0) {
                float dx = pxi - pos[3*e + 0];
                float dy = pyi - pos[3*e + 1];
                float dz = pzi - pos[3*e + 2];
                dx -= Lx * rintf(dx * iLx);
                dy -= Ly * rintf(dy * iLy);
                dz -= Lz * rintf(dz * iLz);
                float r2 = dx*dx + dy*dy + dz*dz;
                if (r2 > 0.f) {
                    float rinv = rsqrtf(r2);
                    float r = r2 * rinv;
                    eacc += -0.5f * COULOMB * qi * q[e] * erff(ALPHA * r) * rinv;
                }
            }
        }
    }

    float wt = (bi == bj) ? 0.5f : 1.0f;
    float tot = COULOMB * wt * pacc + eacc;
#pragma unroll
    for (int off = 16; off > 0; off >>= 1)
        tot += __shfl_down_sync(0xffffffffu, tot, off);
    if ((tx & 31) == 0)
        atomicAdd(&g_edir, (double)tot);
}

// ---------------- B-spline spread (order 4) ----------------
__global__ void k_spread(const float* __restrict__ pos, const float* __restrict__ q, int N) {
    int i = blockIdx.x * blockDim.x + threadIdx.x;
    if (i >= N) return;
    float ib[9];
#pragma unroll
    for (int k = 0; k < 9; k++) ib[k] = g_ib[k];

    float p0 = pos[3*i + 0], p1 = pos[3*i + 1], p2 = pos[3*i + 2];
    float f0 = p0*ib[0] + p1*ib[3] + p2*ib[6];
    float f1 = p0*ib[1] + p1*ib[4] + p2*ib[7];
    float f2 = p0*ib[2] + p1*ib[5] + p2*ib[8];
    f0 -= floorf(f0); f1 -= floorf(f1); f2 -= floorf(f2);

    float u[3] = { f0 * NGRID, f1 * NGRID, f2 * NGRID };
    int   base[3];
    float w[3][4];
#pragma unroll
    for (int d = 0; d < 3; d++) {
        float fu = floorf(u[d]);
        base[d] = (int)fu;
        float t = u[d] - fu;
        float w2_0 = 1.f - t, w2_1 = t;
        float n0 = 0.5f * (1.f - t) * w2_0;
        float n1 = 0.5f * ((t + 1.f) * w2_0 + (2.f - t) * w2_1);
        float n2 = 0.5f * t * w2_1;
        w[d][3] = (1.f/3.f) * t * n2;
        w[d][2] = (1.f/3.f) * ((t + 1.f) * n1 + (3.f - t) * n2);
        w[d][1] = (1.f/3.f) * ((t + 2.f) * n0 + (2.f - t) * n1);
        w[d][0] = (1.f/3.f) * (1.f - t) * n0;
    }
    float qi = q[i];
#pragma unroll
    for (int a = 0; a < 4; a++) {
        int ix = (base[0] + a + 61) & 63;
        float qa = qi * w[0][a];
#pragma unroll
        for (int b = 0; b < 4; b++) {
            int iy = (base[1] + b + 61) & 63;
            float qab = qa * w[1][b];
#pragma unroll
            for (int c = 0; c < 4; c++) {
                int iz = (base[2] + c + 61) & 63;
                int flat = ((ix << 6) | iy) << 6 | iz;
                atomicAdd(&d_grid[flat].x, qab * w[2][c]);
            }
        }
    }
}

// ---------------- register-resident 64-pt DIF FFT (warp collective, out bit-reversed) ----
__device__ __forceinline__ void bfly_local(float2& a, float2& b, float2 w) {
    float dr = a.x - b.x, di = a.y - b.y;
    a.x += b.x; a.y += b.y;
    b.x = dr * w.x - di * w.y;
    b.y = dr * w.y + di * w.x;
}
__device__ __forceinline__ float2 bfly_shfl(float2 v, int len, int lane, float2 w) {
    float ox = __shfl_xor_sync(0xffffffffu, v.x, len);
    float oy = __shfl_xor_sync(0xffffffffu, v.y, len);
    if ((lane & len) == 0) {
        return make_float2(v.x + ox, v.y + oy);
    } else {
        float dr = ox - v.x, di = oy - v.y;
        return make_float2(dr * w.x - di * w.y, dr * w.y + di * w.x);
    }
}
// tw[k] = exp(-i*pi*k/32)
__device__ __forceinline__ void fft64_reg(float2& a, float2& b, int lane,
                                          const float2* __restrict__ tw) {
    bfly_local(a, b, tw[lane]);
#pragma unroll
    for (int len = 16; len >= 1; len >>= 1) {
        float2 w = tw[(lane & (len - 1)) * (32 / len)];
        a = bfly_shfl(a, len, lane, w);
        b = bfly_shfl(b, len, lane, w);
    }
}

// ---------------- fused z + y FFT passes: one CTA per x-plane, 32 warps ----------------
__global__ void __launch_bounds__(1024) k_fft_zy() {
    __shared__ float2 v[64 * 65];
    __shared__ float2 tw[32];
    const int tid  = threadIdx.x;
    const int lane = tid & 31, w = tid >> 5;
    if (tid < 32) {
        float s, c; sincospif((float)tid / 32.f, &s, &c);
        tw[tid] = make_float2(c, -s);
    }
    float2* gp = d_grid + (blockIdx.x << 12);
    for (int k = tid; k < 4096; k += 1024) {
        int y = k >> 6, z = k & 63;
        v[y * 65 + z] = gp[k];
    }
    __syncthreads();
#pragma unroll
    for (int l = 0; l < 2; l++) {
        float2* p = v + (w + 32 * l) * 65;
        float2 a = p[lane], b = p[lane + 32];
        fft64_reg(a, b, lane, tw);
        p[lane] = a; p[lane + 32] = b;
    }
    __syncthreads();
#pragma unroll
    for (int l = 0; l < 2; l++) {
        float2* p = v + (w + 32 * l);
        float2 a = p[lane * 65], b = p[(lane + 32) * 65];
        fft64_reg(a, b, lane, tw);
        p[lane * 65] = a; p[(lane + 32) * 65] = b;
    }
    __syncthreads();
    for (int k = tid; k < 4096; k += 1024) {
        int y = k >> 6, z = k & 63;
        gp[k] = v[y * 65 + z];
    }
}

__device__ __forceinline__ int brev6(int x) { return (int)(__brev((unsigned)x) >> 26); }

__device__ __forceinline__ float recip_contrib(float2 F, int mx, int my, int mz,
                                               const float* bm, const float* ib) {
    float fx = (mx < 32) ? (float)mx : (float)(mx - 64);
    float fy = (my < 32) ? (float)my : (float)(my - 64);
    float fz = (mz < 32) ? (float)mz : (float)(mz - 64);
    float k0 = fx*ib[0] + fy*ib[1] + fz*ib[2];
    float k1 = fx*ib[3] + fy*ib[4] + fz*ib[5];
    float k2 = fx*ib[6] + fy*ib[7] + fz*ib[8];
    float msq = k0*k0 + k1*k1 + k2*k2;
    if (msq <= 0.f) return 0.f;
    float infl = __expf(-(PI_F*PI_F) * msq / (ALPHA*ALPHA)) / msq;
    return infl * bm[mx] * bm[my] * bm[mz] * (F.x*F.x + F.y*F.y);
}

// ---------------- x FFT pass fused with reciprocal reduction ----------------
__global__ void __launch_bounds__(256) k_fft_x_red() {
    __shared__ float2 tw[32];
    __shared__ float  bm[64];
    __shared__ float  ib[9];
    __shared__ float  partial[8];
    const int tid  = threadIdx.x;
    const int lane = tid & 31, w = tid >> 5;
    if (tid < 32) {
        float sn, cs; sincospif((float)tid / 32.f, &sn, &cs);
        tw[tid] = make_float2(cs, -sn);
    }
    if (tid < 64) bm[tid] = g_bmod[tid];
    if (tid < 9)  ib[tid] = g_ib[tid];
    __syncthreads();

    const int line = blockIdx.x * 8 + w;
    float2 a = d_grid[lane * 4096 + line];
    float2 b = d_grid[(lane + 32) * 4096 + line];
    fft64_reg(a, b, lane, tw);

    const int my = brev6(line >> 6);
    const int mz = brev6(line & 63);
    float val = recip_contrib(a, brev6(lane),      my, mz, bm, ib)
              + recip_contrib(b, brev6(lane + 32), my, mz, bm, ib);
#pragma unroll
    for (int off = 16; off > 0; off >>= 1)
        val += __shfl_down_sync(0xffffffffu, val, off);
    if (lane == 0) partial[w] = val;
    __syncthreads();
    if (tid < 8) {
        float x = partial[tid];
#pragma unroll
        for (int off = 4; off > 0; off >>= 1)
            x += __shfl_down_sync(0xffu, x, off);
        if (tid == 0) atomicAdd(&g_erec, (double)x);
    }
}

// ---------------- finalize ----------------
__global__ void k_final(float* __restrict__ out) {
    double V = fabs((double)g_det);
    double erec = (double)COULOMB / (2.0 * 3.14159265358979323846 * V) * g_erec;
    out[0] = (float)(g_edir + erec);
}

// ---------------- launch (fork direct onto side stream, join before final) -------------
extern "C" void kernel_launch(void* const* d_in, const int* in_sizes, int n_in,
                              void* d_out, int out_size) {
    (void)n_in; (void)out_size;
    const float* pos  = (const float*)d_in[0];
    const float* q    = (const float*)d_in[1];
    const float* box  = (const float*)d_in[2];
    const int*   excl = (const int*)d_in[3];
    const int N = in_sizes[1];

    static cudaStream_t s_side = nullptr;
    static cudaEvent_t  ev_fork = nullptr, ev_join = nullptr;
    if (!s_side) {
        cudaStreamCreateWithFlags(&s_side, cudaStreamNonBlocking);
        cudaEventCreateWithFlags(&ev_fork, cudaEventDisableTiming);
        cudaEventCreateWithFlags(&ev_join, cudaEventDisableTiming);
    }

    k_setup<<<NG3 / 256, 256>>>(box);

    cudaEventRecord(ev_fork, 0);
    cudaStreamWaitEvent(s_side, ev_fork, 0);
    dim3 dgrid(N / DTILE, N / DTILE);
    k_direct<<<dgrid, DTILE, 0, s_side>>>(pos, q, excl, N);
    cudaEventRecord(ev_join, s_side);

    k_spread<<<(N + 255) / 256, 256>>>(pos, q, N);
    k_fft_zy<<<64, 1024>>>();
    k_fft_x_red<<<4096 / 8, 256>>>();

    cudaStreamWaitEvent(0, ev_join, 0);
    k_final<<<1, 1>>>((float*)d_out);
}